// round 6
// baseline (speedup 1.0000x reference)
#include <cuda_runtime.h>
#include <cstdint>

#define BB 2
#define SS 2048
#define DD 1024
#define HH 16
#define DHD 64
#define NROWS (BB*SS)          // 4096
#define OUT_ELEMS (BB*SS*DD)   // 4194304
#define ATTN_ELEMS ((long long)HH*BB*SS*SS) // 134217728

// ---------------- scratch (device globals: allowed) ----------------
__device__ float g_q[NROWS * DD];
__device__ float g_k[NROWS * DD];
__device__ float g_v[NROWS * DD];
__device__ float g_concat[NROWS * DD];

// =====================================================================
// tf32 mma.sync helpers (sm_80+ PTX; compiles on plain sm_103 target)
// =====================================================================
__device__ __forceinline__ uint32_t f2tf32(float f) {
    uint32_t r;
    asm("cvt.rn.tf32.f32 %0, %1;" : "=r"(r) : "f"(f));
    return r;
}
__device__ __forceinline__ void mma_tf32(float c[4], const uint32_t a[4],
                                         uint32_t b0, uint32_t b1) {
    asm volatile(
        "mma.sync.aligned.m16n8k8.row.col.f32.tf32.tf32.f32 "
        "{%0,%1,%2,%3}, {%4,%5,%6,%7}, {%8,%9}, {%0,%1,%2,%3};"
        : "+f"(c[0]), "+f"(c[1]), "+f"(c[2]), "+f"(c[3])
        : "r"(a[0]), "r"(a[1]), "r"(a[2]), "r"(a[3]), "r"(b0), "r"(b1));
}

#define KS_STRIDE 68     // [token][e] rows padded: B-frag reads conflict-free
#define PS_STRIDE 132    // [row][col]: A-frag reads conflict-free
// smem floats: KS 128*68, VS 128*68 (doubles as Q staging), PS 128*132
#define SM_KS 0
#define SM_VS (128*KS_STRIDE)
#define SM_PS (2*128*KS_STRIDE)
#define SM_FLOATS (2*128*KS_STRIDE + 128*PS_STRIDE)   // 34304
#define SMEM_TOTAL_B (SM_FLOATS*4)                    // 137216

// =====================================================================
// Fused attention, mma.sync tf32. CTA = 128 q-rows of one (h,b).
// 8 warps x 16 rows. Two passes over K tiles of 128 tokens.
// =====================================================================
__global__ __launch_bounds__(256, 1) void attn_mma(float* __restrict__ attn_out)
{
    extern __shared__ float sm[];
    float* KS = sm + SM_KS;
    float* VS = sm + SM_VS;
    float* PS = sm + SM_PS;

    const int tid  = threadIdx.x;
    const int wid  = tid >> 5;
    const int lane = tid & 31;
    const int g  = lane >> 2;      // groupID (row within octet)
    const int tg = lane & 3;       // thread-in-group (k index)
    const int m0 = wid << 4;       // warp's 16-row base

    const int s0 = blockIdx.x << 7;
    const int b  = blockIdx.y;
    const int h  = blockIdx.z;

    const float* qg = g_q + (size_t)b * SS * DD + h * DHD;
    const float* kg = g_k + (size_t)b * SS * DD + h * DHD;
    const float* vg = g_v + (size_t)b * SS * DD + h * DHD;

    // ---- stage Q (128x64) into VS as tf32, then load A-fragments ----
    #pragma unroll
    for (int i = 0; i < 8; i++) {
        const int idx = tid + (i << 8);
        const int row = idx >> 4;
        const int e0  = (idx & 15) << 2;
        float4 v = *(const float4*)&qg[(size_t)(s0 + row) * DD + e0];
        uint4 t;
        t.x = f2tf32(v.x); t.y = f2tf32(v.y);
        t.z = f2tf32(v.z); t.w = f2tf32(v.w);
        *(uint4*)&VS[row * KS_STRIDE + e0] = t;
    }
    __syncthreads();

    uint32_t qa[8][4];
    #pragma unroll
    for (int ks = 0; ks < 8; ks++) {
        const int base = (m0 + g) * KS_STRIDE + (ks << 3) + tg;
        qa[ks][0] = __float_as_uint(VS[base]);
        qa[ks][1] = __float_as_uint(VS[base + 8 * KS_STRIDE]);
        qa[ks][2] = __float_as_uint(VS[base + 4]);
        qa[ks][3] = __float_as_uint(VS[base + 8 * KS_STRIDE + 4]);
    }
    __syncthreads();

    // ================= pass 1: row sums =================
    float rlo = 0.f, rhi = 0.f;
    for (int t0i = 0; t0i < 16; t0i++) {
        const int t0 = t0i << 7;
        #pragma unroll
        for (int i = 0; i < 8; i++) {
            const int idx = tid + (i << 8);
            const int row = idx >> 4;
            const int e0  = (idx & 15) << 2;
            float4 v = *(const float4*)&kg[(size_t)(t0 + row) * DD + e0];
            uint4 t;
            t.x = f2tf32(v.x); t.y = f2tf32(v.y);
            t.z = f2tf32(v.z); t.w = f2tf32(v.w);
            *(uint4*)&KS[row * KS_STRIDE + e0] = t;
        }
        __syncthreads();

        #pragma unroll
        for (int nt = 0; nt < 16; nt++) {
            float c[4] = {0.f, 0.f, 0.f, 0.f};
            #pragma unroll
            for (int ks = 0; ks < 8; ks++) {
                const int kb = (((nt << 3) + g) * KS_STRIDE) + (ks << 3) + tg;
                mma_tf32(c, qa[ks],
                         __float_as_uint(KS[kb]),
                         __float_as_uint(KS[kb + 4]));
            }
            rlo += __expf(c[0] * 0.125f) + __expf(c[1] * 0.125f);
            rhi += __expf(c[2] * 0.125f) + __expf(c[3] * 0.125f);
        }
        __syncthreads();
    }
    rlo += __shfl_xor_sync(0xffffffffu, rlo, 1);
    rlo += __shfl_xor_sync(0xffffffffu, rlo, 2);
    rhi += __shfl_xor_sync(0xffffffffu, rhi, 1);
    rhi += __shfl_xor_sync(0xffffffffu, rhi, 2);
    const float inv_lo = 1.0f / rlo;
    const float inv_hi = 1.0f / rhi;

    // ================= pass 2: normalize + attn write + P@V =================
    float oc[8][4];
    #pragma unroll
    for (int nt = 0; nt < 8; nt++)
        #pragma unroll
        for (int j = 0; j < 4; j++) oc[nt][j] = 0.f;

    for (int t0i = 0; t0i < 16; t0i++) {
        const int t0 = t0i << 7;
        // load K tile (tf32)
        #pragma unroll
        for (int i = 0; i < 8; i++) {
            const int idx = tid + (i << 8);
            const int row = idx >> 4;
            const int e0  = (idx & 15) << 2;
            float4 v = *(const float4*)&kg[(size_t)(t0 + row) * DD + e0];
            uint4 t;
            t.x = f2tf32(v.x); t.y = f2tf32(v.y);
            t.z = f2tf32(v.z); t.w = f2tf32(v.w);
            *(uint4*)&KS[row * KS_STRIDE + e0] = t;
        }
        // load V tile (tf32)
        #pragma unroll
        for (int i = 0; i < 8; i++) {
            const int idx = tid + (i << 8);
            const int row = idx >> 4;
            const int e0  = (idx & 15) << 2;
            float4 v = *(const float4*)&vg[(size_t)(t0 + row) * DD + e0];
            uint4 t;
            t.x = f2tf32(v.x); t.y = f2tf32(v.y);
            t.z = f2tf32(v.z); t.w = f2tf32(v.w);
            *(uint4*)&VS[row * KS_STRIDE + e0] = t;
        }
        __syncthreads();

        // scores -> P (normalized, fp32) into PS
        #pragma unroll
        for (int nt = 0; nt < 16; nt++) {
            float c[4] = {0.f, 0.f, 0.f, 0.f};
            #pragma unroll
            for (int ks = 0; ks < 8; ks++) {
                const int kb = (((nt << 3) + g) * KS_STRIDE) + (ks << 3) + tg;
                mma_tf32(c, qa[ks],
                         __float_as_uint(KS[kb]),
                         __float_as_uint(KS[kb + 4]));
            }
            const int row = m0 + g;
            const int col = (nt << 3) + (tg << 1);
            *(float2*)&PS[row * PS_STRIDE + col] =
                make_float2(__expf(c[0] * 0.125f) * inv_lo,
                            __expf(c[1] * 0.125f) * inv_lo);
            *(float2*)&PS[(row + 8) * PS_STRIDE + col] =
                make_float2(__expf(c[2] * 0.125f) * inv_hi,
                            __expf(c[3] * 0.125f) * inv_hi);
        }
        __syncthreads();

        // O += P @ V   (A-frags from PS, B-frags from VS)
        #pragma unroll
        for (int ks = 0; ks < 16; ks++) {
            uint32_t a[4];
            const int base = (m0 + g) * PS_STRIDE + (ks << 3) + tg;
            a[0] = __float_as_uint(PS[base]);
            a[1] = __float_as_uint(PS[base + 8 * PS_STRIDE]);
            a[2] = __float_as_uint(PS[base + 4]);
            a[3] = __float_as_uint(PS[base + 8 * PS_STRIDE + 4]);
            #pragma unroll
            for (int nt = 0; nt < 8; nt++) {
                const int vb0 = ((ks << 3) + tg) * KS_STRIDE + (nt << 3) + g;
                mma_tf32(oc[nt], a,
                         __float_as_uint(VS[vb0]),
                         __float_as_uint(VS[vb0 + 4 * KS_STRIDE]));
            }
        }

        // write normalized attn tile (each warp writes full 128-float rows)
        if (attn_out) {
            const size_t gbase = ((size_t)(h * BB + b) * SS + s0) * SS + t0;
            #pragma unroll
            for (int i = 0; i < 16; i++) {
                const int lin = tid + (i << 8);
                const int row = lin >> 5;
                const int c4  = (lin & 31) << 2;
                float4 pv = *(const float4*)&PS[row * PS_STRIDE + c4];
                *(float4*)&attn_out[gbase + (size_t)row * SS + c4] = pv;
            }
        }
        __syncthreads();
    }

    // ---- write O (128 x 64) to g_concat ----
    {
        const size_t row = (size_t)(b * SS + s0 + m0 + g);
        #pragma unroll
        for (int nt = 0; nt < 8; nt++) {
            const int col = h * DHD + (nt << 3) + (tg << 1);
            *(float2*)&g_concat[row * DD + col] =
                make_float2(oc[nt][0], oc[nt][1]);
            *(float2*)&g_concat[(row + 8) * DD + col] =
                make_float2(oc[nt][2], oc[nt][3]);
        }
    }
}

// =====================================================================
// Kernel 1: per-head projections (fp32 SIMT, known-good from R2)
// =====================================================================
__global__ __launch_bounds__(256) void gemm_proj(
    const float* __restrict__ q_in, const float* __restrict__ k_in,
    const float* __restrict__ v_in,
    const float* __restrict__ Wq, const float* __restrict__ Wk,
    const float* __restrict__ Wv)
{
    const int z = blockIdx.z;
    const float* A = (z == 0) ? q_in : ((z == 1) ? k_in : v_in);
    const float* W = (z == 0) ? Wq   : ((z == 1) ? Wk   : Wv);
    float* C       = (z == 0) ? g_q  : ((z == 1) ? g_k  : g_v);

    __shared__ float As[8][128];
    __shared__ float Bs[8][128];

    const int tid  = threadIdx.x;
    const int row0 = blockIdx.x << 7;
    const int col0 = blockIdx.y << 7;
    const int tx = tid & 15, ty = tid >> 4;
    const int m0 = ty << 3, n0 = tx << 3;
    const int lm = tid >> 1;
    const int lk = (tid & 1) << 2;
    const int bk = tid >> 5;
    const int bn = (tid & 31) << 2;

    float acc[8][8] = {};

    for (int k0 = 0; k0 < DD; k0 += 8) {
        float4 av = *(const float4*)&A[(size_t)(row0 + lm) * DD + k0 + lk];
        As[lk + 0][lm] = av.x; As[lk + 1][lm] = av.y;
        As[lk + 2][lm] = av.z; As[lk + 3][lm] = av.w;

        const int n = col0 + bn;
        const int widx = ((n >> 6) * DD + (k0 + bk)) * DHD + (n & 63);
        *(float4*)&Bs[bk][bn] = *(const float4*)&W[widx];
        __syncthreads();

        #pragma unroll
        for (int k = 0; k < 8; k++) {
            float a[8], bb[8];
            *(float4*)&a[0] = *(const float4*)&As[k][m0];
            *(float4*)&a[4] = *(const float4*)&As[k][m0 + 4];
            *(float4*)&bb[0] = *(const float4*)&Bs[k][n0];
            *(float4*)&bb[4] = *(const float4*)&Bs[k][n0 + 4];
            #pragma unroll
            for (int i = 0; i < 8; i++)
                #pragma unroll
                for (int j = 0; j < 8; j++)
                    acc[i][j] = fmaf(a[i], bb[j], acc[i][j]);
        }
        __syncthreads();
    }

    #pragma unroll
    for (int i = 0; i < 8; i++) {
        float* crow = &C[(size_t)(row0 + m0 + i) * DD + col0 + n0];
        *(float4*)&crow[0] = make_float4(acc[i][0], acc[i][1], acc[i][2], acc[i][3]);
        *(float4*)&crow[4] = make_float4(acc[i][4], acc[i][5], acc[i][6], acc[i][7]);
    }
}

// =====================================================================
// Kernel 3: output = concat @ Wo^T (fp32 SIMT, known-good from R2)
// =====================================================================
__global__ __launch_bounds__(256) void gemm_out(
    const float* __restrict__ Wo, float* __restrict__ out)
{
    __shared__ float As[8][128];
    __shared__ float Bs[8][128];

    const int tid  = threadIdx.x;
    const int row0 = blockIdx.x << 7;
    const int col0 = blockIdx.y << 7;
    const int tx = tid & 15, ty = tid >> 4;
    const int m0 = ty << 3, n0 = tx << 3;
    const int lm = tid >> 1;
    const int lk = (tid & 1) << 2;

    float acc[8][8] = {};

    for (int k0 = 0; k0 < DD; k0 += 8) {
        float4 av = *(const float4*)&g_concat[(size_t)(row0 + lm) * DD + k0 + lk];
        As[lk + 0][lm] = av.x; As[lk + 1][lm] = av.y;
        As[lk + 2][lm] = av.z; As[lk + 3][lm] = av.w;
        float4 bv = *(const float4*)&Wo[(size_t)(col0 + lm) * DD + k0 + lk];
        Bs[lk + 0][lm] = bv.x; Bs[lk + 1][lm] = bv.y;
        Bs[lk + 2][lm] = bv.z; Bs[lk + 3][lm] = bv.w;
        __syncthreads();

        #pragma unroll
        for (int k = 0; k < 8; k++) {
            float a[8], bb[8];
            *(float4*)&a[0] = *(const float4*)&As[k][m0];
            *(float4*)&a[4] = *(const float4*)&As[k][m0 + 4];
            *(float4*)&bb[0] = *(const float4*)&Bs[k][n0];
            *(float4*)&bb[4] = *(const float4*)&Bs[k][n0 + 4];
            #pragma unroll
            for (int i = 0; i < 8; i++)
                #pragma unroll
                for (int j = 0; j < 8; j++)
                    acc[i][j] = fmaf(a[i], bb[j], acc[i][j]);
        }
        __syncthreads();
    }

    #pragma unroll
    for (int i = 0; i < 8; i++) {
        float* crow = &out[(size_t)(row0 + m0 + i) * DD + col0 + n0];
        *(float4*)&crow[0] = make_float4(acc[i][0], acc[i][1], acc[i][2], acc[i][3]);
        *(float4*)&crow[4] = make_float4(acc[i][4], acc[i][5], acc[i][6], acc[i][7]);
    }
}

// =====================================================================
extern "C" void kernel_launch(void* const* d_in, const int* in_sizes, int n_in,
                              void* d_out, int out_size)
{
    const float* query = (const float*)d_in[0];
    const float* key   = (const float*)d_in[1];
    const float* value = (const float*)d_in[2];
    const float* Wq    = (const float*)d_in[3];
    const float* Wk    = (const float*)d_in[4];
    const float* Wv    = (const float*)d_in[5];
    const float* Wo    = (const float*)d_in[6];
    float* out = (float*)d_out;

    float* attn_ptr = nullptr;
    if ((long long)out_size >= (long long)OUT_ELEMS + ATTN_ELEMS)
        attn_ptr = out + OUT_ELEMS;

    // 1) projections (fp32 SIMT)
    gemm_proj<<<dim3(NROWS / 128, DD / 128, 3), 256>>>(query, key, value, Wq, Wk, Wv);

    // 2) fused attention (mma.sync tf32)
    cudaFuncSetAttribute(attn_mma, cudaFuncAttributeMaxDynamicSharedMemorySize,
                         SMEM_TOTAL_B);
    attn_mma<<<dim3(SS / 128, BB, HH), 256, SMEM_TOTAL_B>>>(attn_ptr);

    // 3) output projection (fp32 SIMT)
    gemm_out<<<dim3(NROWS / 128, DD / 128), 256>>>(Wo, out);
}